// round 5
// baseline (speedup 1.0000x reference)
#include <cuda_runtime.h>
#include <cstdint>

// Haar IDWT (reference's LH-uses-LPF-twice quirk folded into LL by linearity):
//   out[n,a,b] = 0.5 * ((ll+lh) + sb*hl + sa*sb*hh)
//   sa = (a even ? -1 : +1), sb likewise; (ll,lh,hl,hh) = in[n, a>>1, b>>1, :]
//
// R5: dense warp-strided loads (MLP_p1=4, each LDG.128 = 512B dense) +
// STG.128 stores via one shfl_xor(1) pairing:
//   lanes 2u / 2u+1 hold adjacent pixels of output pair u; after exchanging
//   (e,hl,hh), the even lane emits the pair's TOP-row float4 and the odd lane
//   the BOTTOM-row float4. Each STG.128 covers two dense 256B segments.

namespace {
constexpr int B = 16;
constexpr int H = 512;
constexpr int W = 512;
constexpr int TOTAL = B * H * W / 4;   // 1,048,576 threads (4 pixels each)
}

__global__ void __launch_bounds__(256) idwt_haar_kernel(
    const float4* __restrict__ in, float4* __restrict__ out)
{
    int tid  = blockIdx.x * 256 + threadIdx.x;
    int lane = threadIdx.x & 31;
    int warp = tid >> 5;
    int base = (warp << 7) + lane;          // pixel index for k=0

    // front-batched dense loads (each instruction: 32 lanes x 16B = 512B)
    float4 p0 = in[base];
    float4 p1 = in[base + 32];
    float4 p2 = in[base + 64];
    float4 p3 = in[base + 96];

    // all 4 pixels share (n, r); 128-pixel warp segments never straddle a row
    int n    = base >> 18;
    int r    = (base >> 9) & (H - 1);
    int col0 = base & (W - 1);              // input col of this lane's k=0 pixel

    bool odd = lane & 1;
    // even lane: top row (a=2r), pair starts at its own col (col0 even)
    // odd  lane: bottom row (a=2r+1), pair starts at col0-1
    int pcol = odd ? (col0 - 1) : col0;     // even pair-start column
    size_t orow = ((size_t)n << 10) + 2 * r + (odd ? 1 : 0);
    size_t o4   = (orow << 8) + (pcol >> 1);  // float4 index in output

    float4 p[4] = {p0, p1, p2, p3};
#pragma unroll
    for (int k = 0; k < 4; k++) {
        float e  = 0.5f * (p[k].x + p[k].y);
        float hl = 0.5f * p[k].z;
        float hh = 0.5f * p[k].w;
        float ne  = __shfl_xor_sync(0xffffffffu, e,  1);
        float nhl = __shfl_xor_sync(0xffffffffu, hl, 1);
        float nhh = __shfl_xor_sync(0xffffffffu, hh, 1);

        float4 v;
        if (!odd) {
            // top row, sa=-1: even col -> e-hl+hh, odd col -> e+hl-hh
            v.x = e  - hl  + hh;   v.y = e  + hl  - hh;
            v.z = ne - nhl + nhh;  v.w = ne + nhl - nhh;
        } else {
            // bottom row, sa=+1; neighbor holds the even pixel of the pair
            v.x = ne - nhl - nhh;  v.y = ne + nhl + nhh;
            v.z = e  - hl  - hh;   v.w = e  + hl  + hh;
        }
        out[o4 + 16 * k] = v;   // +32 pixels = +64 output floats = +16 float4
    }
}

extern "C" void kernel_launch(void* const* d_in, const int* in_sizes, int n_in,
                              void* d_out, int out_size)
{
    const float4* in = (const float4*)d_in[0];
    float4* out = (float4*)d_out;
    idwt_haar_kernel<<<TOTAL / 256, 256>>>(in, out);
}

// round 6
// speedup vs baseline: 1.0793x; 1.0793x over previous
#include <cuda_runtime.h>
#include <cstdint>

// Haar IDWT (reference's LH-uses-LPF-twice quirk folded into LL by linearity).
//
//   out[n,a,b] = 0.5 * ((ll+lh) + sb*hl + sa*sb*hh)
//   sa = (a even ? -1 : +1), sb = (b even ? -1 : +1)
//   (ll,lh,hl,hh) = in[n, a>>1, b>>1, 0..3]   (contiguous float4, channels-last)
//
// R6 = exact R1 (best measured wall, 20.96us; at the compulsory-traffic HBM
// roofline: 134 MB in+out, ~7.6 TB/s achieved during the kernel).
// Each thread handles TWO adjacent input pixels (r, 2c) and (r, 2c+1):
//   loads  : 2x float4 (coalesced), stores : 2x float4 (dense 512B/instr).

namespace {
constexpr int B = 16;
constexpr int H = 512;
constexpr int W = 512;
constexpr int PAIRS_PER_ROW = W / 2;                 // 256
constexpr int TOTAL = B * H * PAIRS_PER_ROW;         // 2,097,152 threads
constexpr int OW = 2 * W;                            // 1024 output width (floats)
}

__global__ void __launch_bounds__(256) idwt_haar_kernel(
    const float4* __restrict__ in, float4* __restrict__ out)
{
    int idx = blockIdx.x * blockDim.x + threadIdx.x;
    if (idx >= TOTAL) return;

    int c = idx & (PAIRS_PER_ROW - 1);       // pair index 0..255
    int r = (idx >> 8) & (H - 1);            // input row 0..511
    int n = idx >> 17;                       // batch 0..15

    const float4* rowp = in + ((size_t)n * H + r) * W;
    float4 p0 = rowp[2 * c];
    float4 p1 = rowp[2 * c + 1];

    // halved components
    float e0  = 0.5f * (p0.x + p0.y);
    float hl0 = 0.5f * p0.z;
    float hh0 = 0.5f * p0.w;
    float e1  = 0.5f * (p1.x + p1.y);
    float hl1 = 0.5f * p1.z;
    float hh1 = 0.5f * p1.w;

    // top row (a = 2r, even -> sa = -1); cols: even b -> sb=-1, odd b -> sb=+1
    float4 top, bot;
    top.x = e0 - hl0 + hh0;   // (2r,   4c  )  b even
    top.y = e0 + hl0 - hh0;   // (2r,   4c+1)  b odd
    top.z = e1 - hl1 + hh1;   // (2r,   4c+2)
    top.w = e1 + hl1 - hh1;   // (2r,   4c+3)
    // bottom row (a = 2r+1, odd -> sa = +1)
    bot.x = e0 - hl0 - hh0;   // (2r+1, 4c  )
    bot.y = e0 + hl0 + hh0;   // (2r+1, 4c+1)
    bot.z = e1 - hl1 - hh1;   // (2r+1, 4c+2)
    bot.w = e1 + hl1 + hh1;   // (2r+1, 4c+3)

    // output float4 index: ((n*1024 + 2r)*1024 + 4c) / 4
    size_t o4 = ((size_t)n * 1024 + 2 * r) * (OW / 4) + c;
    out[o4]            = top;
    out[o4 + OW / 4]   = bot;   // next output row (+1024 floats = +256 float4)
}

extern "C" void kernel_launch(void* const* d_in, const int* in_sizes, int n_in,
                              void* d_out, int out_size)
{
    const float4* in = (const float4*)d_in[0];
    float4* out = (float4*)d_out;
    dim3 block(256);
    dim3 grid((TOTAL + 255) / 256);
    idwt_haar_kernel<<<grid, block>>>(in, out);
}